// round 1
// baseline (speedup 1.0000x reference)
#include <cuda_runtime.h>
#include <cuda_bf16.h>

// Problem constants
#define B_   4
#define S_   16
#define H_   32
#define W_   32
#define CL_  64      // LSTM channels per layer (gates = 4*CL_ = 256)
#define TILE_H 8
#define NTHREADS 256
#define CHUNK 16

// Intermediate layer-0 hidden state: (B,S,64,H,W) fp32 = 16 MB, static device scratch.
__device__ float g_h0[(size_t)B_ * S_ * CL_ * H_ * W_];

__device__ __forceinline__ float sigm(float x) {
    return 1.0f / (1.0f + __expf(-x));
}

// One fused minLSTM layer.
// Block = 256 threads = one 8x32 spatial tile, one batch, one group of 4 LSTM
// channels (=> 16 gate channels: i,f,o,cand x 4). Loops over the S=16 frames
// keeping cell state in registers; conv gates computed from smem-staged input
// chunks of 16 input channels.
template <int CIN>
__device__ __forceinline__ void layer_body(const float* __restrict__ x,
                                           const float* __restrict__ w,
                                           const float* __restrict__ bias,
                                           float* __restrict__ out)
{
    __shared__ float s_in[CHUNK * (TILE_H + 2) * (W_ + 2)]; // 16*10*34 = 5440 floats
    __shared__ float s_w[CHUNK * 9 * 16];                   // [ci][tap][gate16] = 2304 floats
    __shared__ float s_b[16];

    const int tid  = threadIdx.x;
    const int ty   = tid >> 5;       // 0..7
    const int tx   = tid & 31;       // 0..31
    const int tile = blockIdx.x;     // 0..3 (row tiles of 8)
    const int grp  = blockIdx.y;     // 0..15 (4 LSTM channels each)
    const int b    = blockIdx.z;     // 0..3
    const int row0 = tile * TILE_H;
    const int py   = row0 + ty;
    const int px   = tx;

    if (tid < 16) {
        int g = tid >> 2, cc = tid & 3;
        s_b[tid] = bias[g * CL_ + grp * 4 + cc];
    }
    __syncthreads();

    float bj[16];
#pragma unroll
    for (int j = 0; j < 16; ++j) bj[j] = s_b[j];

    // cell state init: reference uses c0 = 0.5 everywhere
    float c0 = 0.5f, c1 = 0.5f, c2 = 0.5f, c3 = 0.5f;

    for (int s = 0; s < S_; ++s) {
        float acc[16];
#pragma unroll
        for (int j = 0; j < 16; ++j) acc[j] = bj[j];

        const float* xin = x + (size_t)(b * S_ + s) * CIN * (H_ * W_);

        for (int ch = 0; ch < CIN / CHUNK; ++ch) {
            // ---- stage input tile (16 ci x 10 rows x 34 cols, zero-padded halo) ----
            for (int i = tid; i < CHUNK * (TILE_H + 2) * (W_ + 2); i += NTHREADS) {
                int ci  = i / ((TILE_H + 2) * (W_ + 2));
                int rem = i % ((TILE_H + 2) * (W_ + 2));
                int r   = rem / (W_ + 2);
                int cl  = rem % (W_ + 2);
                int gy  = row0 - 1 + r;
                int gx  = cl - 1;
                float v = 0.0f;
                if (gy >= 0 && gy < H_ && gx >= 0 && gx < W_)
                    v = xin[(ch * CHUNK + ci) * (H_ * W_) + gy * W_ + gx];
                s_in[i] = v;
            }
            // ---- stage weights: s_w[(ci*9 + tap)*16 + j], j = gate*4 + cc ----
            for (int i = tid; i < CHUNK * 9 * 16; i += NTHREADS) {
                int j   = i & 15;
                int t   = i >> 4;
                int tap = t % 9;
                int ci  = t / 9;
                int g   = j >> 2, cc = j & 3;
                int oc  = g * CL_ + grp * 4 + cc;
                s_w[i] = w[((size_t)oc * CIN + ch * CHUNK + ci) * 9 + tap];
            }
            __syncthreads();

            // ---- accumulate: per tap 1 x-load + 4 broadcast w-float4 -> 16 FFMA ----
            for (int ci = 0; ci < CHUNK; ++ci) {
                const float* xrow = &s_in[ci * (TILE_H + 2) * (W_ + 2)];
#pragma unroll
                for (int ky = 0; ky < 3; ++ky) {
#pragma unroll
                    for (int kx = 0; kx < 3; ++kx) {
                        float xv = xrow[(ty + ky) * (W_ + 2) + tx + kx];
                        const float4* wp = (const float4*)&s_w[(ci * 9 + ky * 3 + kx) * 16];
                        float4 wa = wp[0], wb = wp[1], wc = wp[2], wd = wp[3];
                        acc[0]  += xv * wa.x; acc[1]  += xv * wa.y;
                        acc[2]  += xv * wa.z; acc[3]  += xv * wa.w;
                        acc[4]  += xv * wb.x; acc[5]  += xv * wb.y;
                        acc[6]  += xv * wb.z; acc[7]  += xv * wb.w;
                        acc[8]  += xv * wc.x; acc[9]  += xv * wc.y;
                        acc[10] += xv * wc.z; acc[11] += xv * wc.w;
                        acc[12] += xv * wd.x; acc[13] += xv * wd.y;
                        acc[14] += xv * wd.z; acc[15] += xv * wd.w;
                    }
                }
            }
            __syncthreads();
        }

        // ---- gating + scan step + output ----
        float* outp = out + ((size_t)(b * S_ + s) * CL_ + grp * 4) * (H_ * W_) + py * W_ + px;
#pragma unroll
        for (int cc = 0; cc < 4; ++cc) {
            float it = sigm(acc[cc]);
            float ft = sigm(acc[4 + cc]);
            float ot = sigm(acc[8 + cc]);
            float cd = acc[12 + cc];
            float gd = (cd >= 0.0f) ? (cd + 0.5f) : sigm(cd);
            float inv = 1.0f / (it + ft);
            float fp  = ft * inv;
            float ig  = it * inv * gd;
            float cprev = (cc == 0) ? c0 : (cc == 1) ? c1 : (cc == 2) ? c2 : c3;
            float cn = fp * cprev + ig;
            if (cc == 0) c0 = cn; else if (cc == 1) c1 = cn; else if (cc == 2) c2 = cn; else c3 = cn;
            outp[cc * (H_ * W_)] = ot * cn;
        }
    }
}

__global__ void __launch_bounds__(256)
k_layer0(const float* __restrict__ x, const float* __restrict__ w,
         const float* __restrict__ b)
{
    layer_body<32>(x, w, b, g_h0);
}

__global__ void __launch_bounds__(256)
k_layer1(const float* __restrict__ w, const float* __restrict__ b,
         float* __restrict__ out)
{
    layer_body<64>(g_h0, w, b, out);
}

extern "C" void kernel_launch(void* const* d_in, const int* in_sizes, int n_in,
                              void* d_out, int out_size)
{
    const float* x  = (const float*)d_in[0];
    const float* w0 = (const float*)d_in[1];
    const float* b0 = (const float*)d_in[2];
    const float* w1 = (const float*)d_in[3];
    const float* b1 = (const float*)d_in[4];
    float* out = (float*)d_out;

    dim3 grid(4, 16, 4);   // spatial tiles x channel groups x batch
    k_layer0<<<grid, NTHREADS>>>(x, w0, b0);
    k_layer1<<<grid, NTHREADS>>>(w1, b1, out);
}